// round 13
// baseline (speedup 1.0000x reference)
#include <cuda_runtime.h>
#include <math_constants.h>
#include <cstdint>

#define D_DIM   64
#define K_CODES 512
#define HW      4096
#define N_PIX   131072              // 32*64*64
#define NQ      8388608             // 32*64*64*64
#define ENC_SZ  ((long long)N_PIX * K_CODES)   // 67108864

// ---------------- device globals (no allocation allowed) ----------------
__device__ double   g_loss_acc;
__device__ int      g_flag_cnt;
__device__ float    g_Bs[K_CODES];
__device__ __align__(16) uint32_t g_Wfrag[K_CODES * D_DIM]; // tf32 bits, B-frag order
__device__ __align__(16) float    g_Wt[D_DIM * K_CODES];    // transposed [d][k] fp32
__device__ unsigned g_list[N_PIX];
__device__ int      g_k1[N_PIX];            // approx argmax per pixel
__device__ float    g_gap[N_PIX];           // top-2 gap per pixel

__device__ __forceinline__ uint32_t f2tf32(float f) {
    uint32_t o;
    asm("cvt.rna.tf32.f32 %0, %1;" : "=r"(o) : "f"(f));
    return o;
}

__device__ __forceinline__ void mma_tf32(float& d0, float& d1, float& d2, float& d3,
                                         uint32_t a0, uint32_t a1, uint32_t a2, uint32_t a3,
                                         uint32_t b0, uint32_t b1) {
    asm volatile(
        "mma.sync.aligned.m16n8k8.row.col.f32.tf32.tf32.f32 "
        "{%0,%1,%2,%3}, {%4,%5,%6,%7}, {%8,%9}, {%0,%1,%2,%3};"
        : "+f"(d0), "+f"(d1), "+f"(d2), "+f"(d3)
        : "r"(a0), "r"(a1), "r"(a2), "r"(a3), "r"(b0), "r"(b1));
}

// ---------------- prep: Bs + fragment layout + transposed codebook ----------------
__global__ void prep_kernel(const float* __restrict__ W) {
    int idx = blockIdx.x * 512 + threadIdx.x;   // 64 x 512 = 32768
    // B fragment order (PTX mma.m16n8k8, B col-major 8x8 per step)
    {
        int v    = idx & 3;
        int lane = (idx >> 2) & 31;
        int j    = (idx >> 7) & 3;
        int c    = idx >> 9;
        int s  = 2 * j + (v >> 1);
        int k  = s * 8 + (lane & 3) + ((v & 1) ? 4 : 0);
        int n  = c * 8 + (lane >> 2);
        g_Wfrag[idx] = f2tf32(W[n * D_DIM + k]);
    }
    // transposed [d][k] fp32 for rescore
    {
        int d = idx >> 9, k = idx & 511;
        g_Wt[idx] = W[k * D_DIM + d];
    }
    // ||e_k||^2 (block 0), d ascending = reference order
    if (blockIdx.x == 0) {
        int k = threadIdx.x;
        float b = 0.0f;
        #pragma unroll
        for (int d = 0; d < D_DIM; d++) { float w = W[k * D_DIM + d]; b += w * w; }
        g_Bs[k] = b;
        if (k == 0) { g_loss_acc = 0.0; g_flag_cnt = 0; }
    }
}

__global__ void finalize_kernel(float* out_loss) {
    *out_loss = (float)(2.0 * g_loss_acc / (double)NQ);
}

// ---------------- MMA kernel: 128-pixel tile, 8 warps, smem = X tile only ----------------
__global__ void __launch_bounds__(256, 2)
vq_mma_kernel(const float* __restrict__ X)
{
    __shared__ uint32_t xs[128 * 65];     // x tile tf32, [m][d] stride 65
    __shared__ float    Bss[K_CODES];

    const int tid  = threadIdx.x;
    const int lane = tid & 31, warp = tid >> 5;
    const int tile = blockIdx.x;                 // 1024 tiles of 128 pixels
    const int bidx = tile >> 5;                  // batch
    const int hw0  = (tile & 31) << 7;

    for (int i = tid; i < K_CODES; i += 256) Bss[i] = g_Bs[i];

    const float* Xb = X + (size_t)bidx * (D_DIM * HW) + hw0;
    for (int i = tid; i < 128 * D_DIM; i += 256) {
        int d = i >> 7, m = i & 127;
        xs[m * 65 + d] = f2tf32(Xb[(size_t)d * HW + m]);
    }
    __syncthreads();

    const int g = lane >> 2, t = lane & 3;
    const int row0 = warp * 16;
    // A fragments (m16n8k8): a0(r=g,k=t) a1(r=g+8,k=t) a2(r=g,k=t+4) a3(r=g+8,k=t+4)
    uint32_t a[8][4];
    #pragma unroll
    for (int s = 0; s < 8; s++) {
        int klo = s * 8 + t;
        a[s][0] = xs[(row0 + g)     * 65 + klo];
        a[s][1] = xs[(row0 + g + 8) * 65 + klo];
        a[s][2] = xs[(row0 + g)     * 65 + klo + 4];
        a[s][3] = xs[(row0 + g + 8) * 65 + klo + 4];
    }

    float m1lo = -CUDART_INF_F, m2lo = -CUDART_INF_F;
    float m1hi = -CUDART_INF_F, m2hi = -CUDART_INF_F;
    int   k1lo = 0, k1hi = 0;

    const uint4*  Wf4 = (const uint4*)g_Wfrag;    // L1/L2-broadcast global reads
    const float2* Bs2 = (const float2*)Bss;

    #pragma unroll 2
    for (int c = 0; c < 64; c++) {
        uint4 bq[4];
        #pragma unroll
        for (int j = 0; j < 4; j++) bq[j] = __ldg(&Wf4[(c * 4 + j) * 32 + lane]);

        float d0 = 0.f, d1 = 0.f, d2 = 0.f, d3 = 0.f;
        #pragma unroll
        for (int j = 0; j < 4; j++) {
            mma_tf32(d0, d1, d2, d3, a[2*j][0],   a[2*j][1],   a[2*j][2],   a[2*j][3],   bq[j].x, bq[j].y);
            mma_tf32(d0, d1, d2, d3, a[2*j+1][0], a[2*j+1][1], a[2*j+1][2], a[2*j+1][3], bq[j].z, bq[j].w);
        }
        // acc cols: n = 8c + 2t, 8c + 2t + 1 ; rows g / g+8
        float2 Bv = Bs2[c * 4 + t];
        int n = c * 8 + 2 * t;
        float v0 = fmaf(2.0f, d0, -Bv.x);
        float v1 = fmaf(2.0f, d1, -Bv.y);
        float v2 = fmaf(2.0f, d2, -Bv.x);
        float v3 = fmaf(2.0f, d3, -Bv.y);
        if (v0 > m1lo) { m2lo = m1lo; m1lo = v0; k1lo = n; }     else m2lo = fmaxf(m2lo, v0);
        if (v1 > m1lo) { m2lo = m1lo; m1lo = v1; k1lo = n + 1; } else m2lo = fmaxf(m2lo, v1);
        if (v2 > m1hi) { m2hi = m1hi; m1hi = v2; k1hi = n; }     else m2hi = fmaxf(m2hi, v2);
        if (v3 > m1hi) { m2hi = m1hi; m1hi = v3; k1hi = n + 1; } else m2hi = fmaxf(m2hi, v3);
    }

    // merge top-2 across the 4 lanes of the quad (cols are disjoint)
    #pragma unroll
    for (int off = 1; off <= 2; off <<= 1) {
        float om1 = __shfl_xor_sync(0xffffffffu, m1lo, off);
        float om2 = __shfl_xor_sync(0xffffffffu, m2lo, off);
        int   ok1 = __shfl_xor_sync(0xffffffffu, k1lo, off);
        if (om1 > m1lo) { m2lo = fmaxf(m1lo, om2); m1lo = om1; k1lo = ok1; }
        else            { m2lo = fmaxf(m2lo, om1); }
        om1 = __shfl_xor_sync(0xffffffffu, m1hi, off);
        om2 = __shfl_xor_sync(0xffffffffu, m2hi, off);
        ok1 = __shfl_xor_sync(0xffffffffu, k1hi, off);
        if (om1 > m1hi) { m2hi = fmaxf(m1hi, om2); m1hi = om1; k1hi = ok1; }
        else            { m2hi = fmaxf(m2hi, om1); }
    }
    if (t == 0) {
        int p0 = tile * 128;
        g_k1[p0 + row0 + g]      = k1lo;  g_gap[p0 + row0 + g]      = m1lo - m2lo;
        g_k1[p0 + row0 + g + 8]  = k1hi;  g_gap[p0 + row0 + g + 8]  = m1hi - m2hi;
    }
}

// ---------------- epilogue: margin + q/idx/loss/flags + fused enc fill ----------------
__global__ void __launch_bounds__(512, 2)
epilogue_kernel(const float* __restrict__ X, const float* __restrict__ W,
                float* __restrict__ out_q, float* __restrict__ out_enc,
                float* __restrict__ out_idx_f)
{
    __shared__ int sk1[512];

    const int tid = threadIdx.x;
    const int p   = blockIdx.x * 512 + tid;
    const int bb  = p >> 12, hw = p & 4095;

    int   k1  = g_k1[p];
    float gap = g_gap[p];
    sk1[tid] = k1;

    // pass 1: sab / A2 (x stays hot in L1 for pass 2)
    const float* xp = X + (size_t)bb * (D_DIM * HW) + hw;
    float sab = 0.0f, A2 = 0.0f;
    #pragma unroll
    for (int d = 0; d < D_DIM; d++) {
        float xv = xp[(size_t)d * HW];
        sab += fabsf(xv);
        A2  += xv * xv;
    }
    float margin = 6e-6f * sab + 4e-7f * A2 + 5e-5f;
    bool  flag   = (gap <= margin);

    float lsum = 0.0f;
    if (!flag) {
        const float* wr = W + (size_t)k1 * D_DIM;
        float* qb = out_q ? out_q + (size_t)bb * (D_DIM * HW) + hw : nullptr;
        #pragma unroll
        for (int d = 0; d < D_DIM; d++) {
            float xv   = xp[(size_t)d * HW];      // L1 hit
            float diff = wr[d] - xv;              // fl(q - x), as reference
            if (qb) qb[(size_t)d * HW] = xv + diff;
            lsum += diff * diff;
        }
        if (out_idx_f) out_idx_f[p] = (float)k1;
    } else {
        int pos = atomicAdd(&g_flag_cnt, 1);
        g_list[pos] = ((unsigned)p << 10) | (unsigned)k1;
    }
    #pragma unroll
    for (int off = 16; off > 0; off >>= 1)
        lsum += __shfl_xor_sync(0xffffffffu, lsum, off);
    if ((tid & 31) == 0) atomicAdd(&g_loss_acc, (double)lsum);

    // fused enc fill for this block's 512 rows (alignment-safe wide stores)
    __syncthreads();
    if (out_enc) {
        const int r = (int)(((uintptr_t)out_enc >> 2) & 3);
        const int h = (4 - r) & 3;
        const int ngroups = (K_CODES - h) >> 2;
        const size_t row0 = (size_t)blockIdx.x * 512;
        for (int i = tid; i < 512 * 128; i += 512) {
            int row = i >> 7, q = i & 127;
            int b = sk1[row];
            float* rb = out_enc + (row0 + row) * K_CODES;
            if (q < ngroups) {
                int e0 = h + 4 * q;
                float4 v = make_float4(0.f, 0.f, 0.f, 0.f);
                int dk = b - e0;
                if ((unsigned)dk < 4u) ((float*)&v)[dk] = 1.0f;
                *(float4*)(rb + e0) = v;
            } else if (q == ngroups) {
                #pragma unroll
                for (int e = 0; e < 3; e++)
                    if (e < h) rb[e] = (b == e) ? 1.0f : 0.0f;
                for (int e = h + 4 * ngroups; e < K_CODES; e++)
                    rb[e] = (b == e) ? 1.0f : 0.0f;
            }
        }
    }
}

// ---------------- exact rescore: 4 pixels/warp, codebook via L1-broadcast LDG ----------------
#define RS_BLOCKS 592
#define RS_WPB    4                 // 128 threads

__global__ void __launch_bounds__(128, 4)
rescore_kernel(const float* __restrict__ X, const float* __restrict__ W,
               float* __restrict__ out_q, float* __restrict__ out_enc,
               float* __restrict__ out_idx_f)
{
    const int cnt = g_flag_cnt;
    if (cnt == 0) return;
    const int ngrp = (cnt + 3) >> 2;
    if ((int)blockIdx.x * RS_WPB >= ngrp) return;

    __shared__ float xwb[RS_WPB * 256];   // [warp][d*4 + j]
    const int tid = threadIdx.x, lid = tid & 31, warp = tid >> 5;
    float* xw = xwb + warp * 256;

    for (int g = blockIdx.x * RS_WPB + warp; g < ngrp; g += RS_BLOCKS * RS_WPB) {
        int base = g * 4;
        unsigned e0 = g_list[base];
        int pe[4], ke[4]; bool valid[4];
        #pragma unroll
        for (int j = 0; j < 4; j++) {
            valid[j] = (base + j < cnt);
            unsigned e = valid[j] ? g_list[base + j] : e0;
            pe[j] = (int)(e >> 10); ke[j] = (int)(e & 1023u);
        }

        // stage x for the 4 pixels: xw[d*4 + j]
        for (int idx = lid; idx < 256; idx += 32) {
            int d = idx >> 2, j = idx & 3;
            int p = pe[j], bb = p >> 12, hw = p & 4095;
            xw[idx] = X[(size_t)bb * (D_DIM * HW) + (size_t)d * HW + hw];
        }
        __syncwarp();

        // A[j] = ||x||^2, exact ascending (lane j computes pixel j)
        float Aj = 0.0f;
        if (lid < 4) {
            #pragma unroll
            for (int d = 0; d < D_DIM; d++) {
                float xv = xw[d * 4 + lid];
                Aj += xv * xv;
            }
        }
        float A[4];
        #pragma unroll
        for (int j = 0; j < 4; j++) A[j] = __shfl_sync(0xffffffffu, Aj, j);

        // 64 accumulators: s[j][i], code k = lid + 32i; fmaf ascending in d
        float s[4][16];
        #pragma unroll
        for (int j = 0; j < 4; j++)
            #pragma unroll
            for (int i = 0; i < 16; i++) s[j][i] = 0.0f;

        for (int d = 0; d < D_DIM; d++) {
            float xv[4];
            #pragma unroll
            for (int j = 0; j < 4; j++) xv[j] = xw[d * 4 + j];   // smem broadcast
            const float* wr = g_Wt + d * K_CODES + lid;          // L1-broadcast LDG
            #pragma unroll
            for (int i = 0; i < 16; i++) {
                float wv = __ldg(&wr[i * 32]);
                #pragma unroll
                for (int j = 0; j < 4; j++) s[j][i] = fmaf(xv[j], wv, s[j][i]);
            }
        }

        // per pixel: first strict min over k, lexicographic across lanes
        #pragma unroll
        for (int j = 0; j < 4; j++) {
            float bd = CUDART_INF_F; int bk = 0;
            #pragma unroll
            for (int i = 0; i < 16; i++) {
                int k = lid + (i << 5);
                float t = (A[j] + g_Bs[k]) - 2.0f * s[j][i];
                if (t < bd) { bd = t; bk = k; }
            }
            #pragma unroll
            for (int off = 16; off > 0; off >>= 1) {
                float od = __shfl_xor_sync(0xffffffffu, bd, off);
                int   ok = __shfl_xor_sync(0xffffffffu, bk, off);
                if (od < bd || (od == bd && ok < bk)) { bd = od; bk = ok; }
            }

            float lsum = 0.0f;
            if (valid[j]) {
                int p = pe[j], bb = p >> 12, hw = p & 4095;
                if (lid == 0) {
                    if (out_idx_f) out_idx_f[p] = (float)bk;
                    if (out_enc && bk != ke[j]) {
                        out_enc[(size_t)p * K_CODES + ke[j]] = 0.0f;
                        out_enc[(size_t)p * K_CODES + bk]   = 1.0f;
                    }
                }
                float* qb = out_q ? out_q + (size_t)bb * (D_DIM * HW) + hw : nullptr;
                #pragma unroll
                for (int u = 0; u < 2; u++) {
                    int d = lid + 32 * u;
                    float diff = W[(size_t)bk * D_DIM + d] - xw[d * 4 + j];
                    if (qb) qb[(size_t)d * HW] = xw[d * 4 + j] + diff;
                    lsum += diff * diff;
                }
            }
            #pragma unroll
            for (int off = 16; off > 0; off >>= 1)
                lsum += __shfl_xor_sync(0xffffffffu, lsum, off);
            if (lid == 0 && valid[j]) atomicAdd(&g_loss_acc, (double)lsum);
        }
        __syncwarp();
    }
}

// ---------------- launch ----------------
extern "C" void kernel_launch(void* const* d_in, const int* in_sizes, int n_in,
                              void* d_out, int out_size)
{
    const float* X = (const float*)d_in[0];
    const float* W = (const float*)d_in[1];
    float* out = (float*)d_out;

    const long long os = (long long)out_size;
    const long long FULL    = 1LL + NQ + ENC_SZ + N_PIX;
    const long long NO_LOSS = (long long)NQ + ENC_SZ + N_PIX;

    float* p_loss = nullptr; float* p_q = nullptr;
    float* p_enc  = nullptr; float* p_idxf = nullptr;

    if (os == FULL) {
        p_loss = out; p_q = out + 1; p_enc = out + 1 + NQ;
        p_idxf = out + 1 + NQ + ENC_SZ;
    } else if (os == NO_LOSS) {
        p_q = out; p_enc = out + NQ; p_idxf = out + NQ + ENC_SZ;
    } else if (os == NQ) {
        p_q = out;
    } else if (os == 1) {
        p_loss = out;
    } else {
        p_loss = out; p_q = out + 1;
        if (os >= 1 + NQ + ENC_SZ) p_enc = out + 1 + NQ;
        if (os >= FULL) p_idxf = out + 1 + NQ + ENC_SZ;
    }

    prep_kernel<<<64, 512>>>(W);
    vq_mma_kernel<<<N_PIX / 128, 256>>>(X);
    epilogue_kernel<<<N_PIX / 512, 512>>>(X, W, p_q, p_enc, p_idxf);
    rescore_kernel<<<RS_BLOCKS, 128>>>(X, W, p_q, p_enc, p_idxf);
    if (p_loss) finalize_kernel<<<1, 1>>>(p_loss);
}

// round 14
// speedup vs baseline: 1.0958x; 1.0958x over previous
#include <cuda_runtime.h>
#include <math_constants.h>
#include <cstdint>

#define D_DIM   64
#define K_CODES 512
#define HW      4096
#define N_PIX   131072              // 32*64*64
#define NQ      8388608             // 32*64*64*64
#define ENC_SZ  ((long long)N_PIX * K_CODES)   // 67108864

// ---------------- device globals (no allocation allowed) ----------------
__device__ double   g_loss_acc;
__device__ int      g_flag_cnt;
__device__ float    g_Bs[K_CODES];
__device__ __align__(16) uint32_t g_Wfrag[K_CODES * D_DIM]; // tf32 bits, B-frag order
__device__ __align__(16) float    g_Wt[D_DIM * K_CODES];    // transposed [d][k] fp32
__device__ unsigned g_list[N_PIX];

__device__ __forceinline__ uint32_t f2tf32(float f) {
    uint32_t o;
    asm("cvt.rna.tf32.f32 %0, %1;" : "=r"(o) : "f"(f));
    return o;
}

__device__ __forceinline__ void mma_tf32(float& d0, float& d1, float& d2, float& d3,
                                         uint32_t a0, uint32_t a1, uint32_t a2, uint32_t a3,
                                         uint32_t b0, uint32_t b1) {
    asm volatile(
        "mma.sync.aligned.m16n8k8.row.col.f32.tf32.tf32.f32 "
        "{%0,%1,%2,%3}, {%4,%5,%6,%7}, {%8,%9}, {%0,%1,%2,%3};"
        : "+f"(d0), "+f"(d1), "+f"(d2), "+f"(d3)
        : "r"(a0), "r"(a1), "r"(a2), "r"(a3), "r"(b0), "r"(b1));
}

// ---------------- prep (merged): Bs + fragment layout + transposed codebook ----------------
__global__ void prep_kernel(const float* __restrict__ W) {
    int idx = blockIdx.x * 512 + threadIdx.x;   // 64 x 512 = 32768
    // B fragment order (PTX mma.m16n8k8, B col-major 8x8 per step)
    {
        int v    = idx & 3;
        int lane = (idx >> 2) & 31;
        int j    = (idx >> 7) & 3;
        int c    = idx >> 9;
        int s  = 2 * j + (v >> 1);
        int k  = s * 8 + (lane & 3) + ((v & 1) ? 4 : 0);
        int n  = c * 8 + (lane >> 2);
        g_Wfrag[idx] = f2tf32(W[n * D_DIM + k]);
    }
    // transposed [d][k] fp32 for rescore
    {
        int d = idx >> 9, k = idx & 511;
        g_Wt[idx] = W[k * D_DIM + d];
    }
    // ||e_k||^2 (block 0), d ascending = reference order
    if (blockIdx.x == 0) {
        int k = threadIdx.x;
        float b = 0.0f;
        #pragma unroll
        for (int d = 0; d < D_DIM; d++) { float w = W[k * D_DIM + d]; b += w * w; }
        g_Bs[k] = b;
        if (k == 0) { g_loss_acc = 0.0; g_flag_cnt = 0; }
    }
}

__global__ void finalize_kernel(float* out_loss) {
    *out_loss = (float)(2.0 * g_loss_acc / (double)NQ);
}

// ---------------- smem layout (bytes), main kernel: 256-pixel tile ----------------
#define SM_W     0               // 131072 : Wfrag (tf32 bits)
#define SM_BS    131072          //   2048 : ||e||^2
#define SM_XS    133120          //  66560 : x tile tf32, [256][65]
#define SM_K1    199680          //   1024 : per-pixel approx argmax
#define SM_GAP   200704          //   1024 : per-pixel top-2 gap
#define SM_TOTAL 201728

// ---------------- main kernel: 256 pixels / block, 16 warps (R12 base + dual chains) ----------------
__global__ void __launch_bounds__(512, 1)
vq_mma_kernel(const float* __restrict__ X, const float* __restrict__ W,
              float* __restrict__ out_q, float* __restrict__ out_enc,
              float* __restrict__ out_idx_f)
{
    extern __shared__ char smem[];
    uint32_t* Wf  = (uint32_t*)(smem + SM_W);
    float*    Bss = (float*)(smem + SM_BS);
    uint32_t* xs  = (uint32_t*)(smem + SM_XS);
    int*      sk1 = (int*)(smem + SM_K1);
    float*    sgp = (float*)(smem + SM_GAP);

    const int tid  = threadIdx.x;
    const int lane = tid & 31, warp = tid >> 5;
    const int tile = blockIdx.x;                 // 512 tiles of 256 pixels
    const int bidx = tile >> 4;                  // 16 tiles per batch
    const int hw0  = (tile & 15) << 8;

    // stage codebook fragments (L2-resident, coalesced 16B)
    {
        const uint4* src = (const uint4*)g_Wfrag;
        uint4* dst = (uint4*)Wf;
        #pragma unroll
        for (int i = 0; i < 16; i++) dst[tid + 512 * i] = src[tid + 512 * i];
    }
    for (int i = tid; i < K_CODES; i += 512) Bss[i] = g_Bs[i];

    // stage x tile as tf32, [m][d] stride 65 (conflict-free STS)
    const float* Xb = X + (size_t)bidx * (D_DIM * HW) + hw0;
    for (int i = tid; i < 256 * D_DIM; i += 512) {
        int d = i >> 8, m = i & 255;
        xs[m * 65 + d] = f2tf32(Xb[(size_t)d * HW + m]);
    }
    __syncthreads();

    // ---- phase 1: per-warp 16 rows x 512 codes via mma.sync tf32 ----
    {
        const int g = lane >> 2, t = lane & 3;
        const int row0 = warp * 16;
        // A fragments (m16n8k8): a0(r=g,k=t) a1(r=g+8,k=t) a2(r=g,k=t+4) a3(r=g+8,k=t+4)
        uint32_t a[8][4];
        #pragma unroll
        for (int s = 0; s < 8; s++) {
            int klo = s * 8 + t;
            a[s][0] = xs[(row0 + g)     * 65 + klo];
            a[s][1] = xs[(row0 + g + 8) * 65 + klo];
            a[s][2] = xs[(row0 + g)     * 65 + klo + 4];
            a[s][3] = xs[(row0 + g + 8) * 65 + klo + 4];
        }

        float m1lo = -CUDART_INF_F, m2lo = -CUDART_INF_F;
        float m1hi = -CUDART_INF_F, m2hi = -CUDART_INF_F;
        int   k1lo = 0, k1hi = 0;

        const uint4*  Wf4 = (const uint4*)Wf;
        const float2* Bs2 = (const float2*)Bss;

        #pragma unroll 2
        for (int c = 0; c < 64; c++) {
            uint4 bq[4];
            #pragma unroll
            for (int j = 0; j < 4; j++) bq[j] = Wf4[(c * 4 + j) * 32 + lane];

            // dual accumulator chains: k-steps 0-3 -> chain A, 4-7 -> chain B (ILP)
            float d0a = 0.f, d1a = 0.f, d2a = 0.f, d3a = 0.f;
            float d0b = 0.f, d1b = 0.f, d2b = 0.f, d3b = 0.f;
            #pragma unroll
            for (int j = 0; j < 2; j++) {
                mma_tf32(d0a, d1a, d2a, d3a, a[2*j][0],   a[2*j][1],   a[2*j][2],   a[2*j][3],   bq[j].x, bq[j].y);
                mma_tf32(d0a, d1a, d2a, d3a, a[2*j+1][0], a[2*j+1][1], a[2*j+1][2], a[2*j+1][3], bq[j].z, bq[j].w);
            }
            #pragma unroll
            for (int j = 2; j < 4; j++) {
                mma_tf32(d0b, d1b, d2b, d3b, a[2*j][0],   a[2*j][1],   a[2*j][2],   a[2*j][3],   bq[j].x, bq[j].y);
                mma_tf32(d0b, d1b, d2b, d3b, a[2*j+1][0], a[2*j+1][1], a[2*j+1][2], a[2*j+1][3], bq[j].z, bq[j].w);
            }
            float d0 = d0a + d0b, d1 = d1a + d1b, d2 = d2a + d2b, d3 = d3a + d3b;

            // acc cols: n = 8c + 2t, 8c + 2t + 1 ; rows g / g+8
            float2 Bv = Bs2[c * 4 + t];
            int n = c * 8 + 2 * t;
            float v0 = fmaf(2.0f, d0, -Bv.x);
            float v1 = fmaf(2.0f, d1, -Bv.y);
            float v2 = fmaf(2.0f, d2, -Bv.x);
            float v3 = fmaf(2.0f, d3, -Bv.y);
            if (v0 > m1lo) { m2lo = m1lo; m1lo = v0; k1lo = n; }     else m2lo = fmaxf(m2lo, v0);
            if (v1 > m1lo) { m2lo = m1lo; m1lo = v1; k1lo = n + 1; } else m2lo = fmaxf(m2lo, v1);
            if (v2 > m1hi) { m2hi = m1hi; m1hi = v2; k1hi = n; }     else m2hi = fmaxf(m2hi, v2);
            if (v3 > m1hi) { m2hi = m1hi; m1hi = v3; k1hi = n + 1; } else m2hi = fmaxf(m2hi, v3);
        }

        // merge top-2 across the 4 lanes of the quad (cols are disjoint)
        #pragma unroll
        for (int off = 1; off <= 2; off <<= 1) {
            float om1 = __shfl_xor_sync(0xffffffffu, m1lo, off);
            float om2 = __shfl_xor_sync(0xffffffffu, m2lo, off);
            int   ok1 = __shfl_xor_sync(0xffffffffu, k1lo, off);
            if (om1 > m1lo) { m2lo = fmaxf(m1lo, om2); m1lo = om1; k1lo = ok1; }
            else            { m2lo = fmaxf(m2lo, om1); }
            om1 = __shfl_xor_sync(0xffffffffu, m1hi, off);
            om2 = __shfl_xor_sync(0xffffffffu, m2hi, off);
            ok1 = __shfl_xor_sync(0xffffffffu, k1hi, off);
            if (om1 > m1hi) { m2hi = fmaxf(m1hi, om2); m1hi = om1; k1hi = ok1; }
            else            { m2hi = fmaxf(m2hi, om1); }
        }
        if (t == 0) {
            sk1[row0 + g]     = k1lo;  sgp[row0 + g]     = m1lo - m2lo;
            sk1[row0 + g + 8] = k1hi;  sgp[row0 + g + 8] = m1hi - m2hi;
        }
    }
    __syncthreads();

    // ---- phase 2 (warps 0-7): exact x reload, margin test, outputs / flag list ----
    if (tid < 256) {
        float lsum = 0.0f;
        const int p  = tile * 256 + tid;
        const int bb = p >> 12, hw = p & 4095;
        const float* xp = X + (size_t)bb * (D_DIM * HW) + hw;
        float x[D_DIM], sab = 0.0f, A2 = 0.0f;
        #pragma unroll
        for (int d = 0; d < D_DIM; d++) {
            x[d] = xp[(size_t)d * HW];
            sab += fabsf(x[d]);
            A2  += x[d] * x[d];
        }
        float margin = 6e-6f * sab + 4e-7f * A2 + 5e-5f;
        int   k1   = sk1[tid];
        bool  flag = (sgp[tid] <= margin);

        if (!flag) {
            const float4* wp = (const float4*)(W + (size_t)k1 * D_DIM);
            float* qb = out_q ? out_q + (size_t)bb * (D_DIM * HW) + hw : nullptr;
            #pragma unroll
            for (int q4 = 0; q4 < 16; q4++) {
                float4 w4 = wp[q4];
                float wv[4] = {w4.x, w4.y, w4.z, w4.w};
                #pragma unroll
                for (int j = 0; j < 4; j++) {
                    int d = q4 * 4 + j;
                    float diff = wv[j] - x[d];          // fl(q - x), as reference
                    if (qb) qb[(size_t)d * HW] = x[d] + diff;
                    lsum += diff * diff;
                }
            }
            if (out_idx_f) out_idx_f[p] = (float)k1;
        } else {
            int pos = atomicAdd(&g_flag_cnt, 1);
            g_list[pos] = ((unsigned)p << 10) | (unsigned)k1;
        }
        #pragma unroll
        for (int off = 16; off > 0; off >>= 1)
            lsum += __shfl_xor_sync(0xffffffffu, lsum, off);
        if ((tid & 31) == 0) atomicAdd(&g_loss_acc, (double)lsum);
    }

    // ---- enc rows (fused zero-fill + one-hot), alignment-safe wide stores ----
    // warps 8-15 arrive here immediately and overlap with phase 2.
    if (out_enc) {
        const int r = (int)(((uintptr_t)out_enc >> 2) & 3);
        const int h = (4 - r) & 3;
        const int ngroups = (K_CODES - h) >> 2;
        for (int i = tid; i < 256 * 128; i += 512) {
            int row = i >> 7, q = i & 127;
            int b = sk1[row];
            float* rb = out_enc + (size_t)(tile * 256 + row) * K_CODES;
            if (q < ngroups) {
                int e0 = h + 4 * q;
                float4 v = make_float4(0.f, 0.f, 0.f, 0.f);
                int dk = b - e0;
                if ((unsigned)dk < 4u) ((float*)&v)[dk] = 1.0f;
                *(float4*)(rb + e0) = v;
            } else if (q == ngroups) {
                #pragma unroll
                for (int e = 0; e < 3; e++)
                    if (e < h) rb[e] = (b == e) ? 1.0f : 0.0f;
                for (int e = h + 4 * ngroups; e < K_CODES; e++)
                    rb[e] = (b == e) ? 1.0f : 0.0f;
            }
        }
    }
}

// ---------------- exact rescore: 4 pixels/warp, smem codebook, 12 warps/block ----------------
#define RS_BLOCKS 148
#define RS_WPB    12                  // 384 threads
#define RS_SMEM   (131072 + 2048 + RS_WPB * 1024)   // 145408

__global__ void __launch_bounds__(384, 1)
rescore_kernel(const float* __restrict__ X, const float* __restrict__ W,
               float* __restrict__ out_q, float* __restrict__ out_enc,
               float* __restrict__ out_idx_f)
{
    const int cnt = g_flag_cnt;
    if (cnt == 0) return;
    const int ngrp = (cnt + 3) >> 2;
    if ((int)blockIdx.x * RS_WPB >= ngrp) return;

    extern __shared__ float sm[];
    float* w2  = sm;                      // [d*512 + k] (copied from g_Wt)
    float* Bsp = sm + D_DIM * K_CODES;    // 512
    float* xwb = Bsp + K_CODES;           // [warp][d*4 + j]

    const int tid = threadIdx.x, lid = tid & 31, warp = tid >> 5;
    float* xw = xwb + warp * 256;

    for (int i = tid; i < K_CODES * D_DIM; i += 384)
        w2[i] = g_Wt[i];                  // coalesced copy, no transpose
    for (int i = tid; i < K_CODES; i += 384) Bsp[i] = g_Bs[i];
    __syncthreads();

    for (int g = blockIdx.x * RS_WPB + warp; g < ngrp; g += RS_BLOCKS * RS_WPB) {
        // gather 4 entries (pad with entry 0 of the group)
        int base = g * 4;
        unsigned e0 = g_list[base];
        int pe[4], ke[4]; bool valid[4];
        #pragma unroll
        for (int j = 0; j < 4; j++) {
            valid[j] = (base + j < cnt);
            unsigned e = valid[j] ? g_list[base + j] : e0;
            pe[j] = (int)(e >> 10); ke[j] = (int)(e & 1023u);
        }

        // stage x for the 4 pixels: xw[d*4 + j]
        for (int idx = lid; idx < 256; idx += 32) {
            int d = idx >> 2, j = idx & 3;
            int p = pe[j], bb = p >> 12, hw = p & 4095;
            xw[idx] = X[(size_t)bb * (D_DIM * HW) + (size_t)d * HW + hw];
        }
        __syncwarp();

        // A[j] = ||x||^2, exact ascending (lane j computes pixel j)
        float Aj = 0.0f;
        if (lid < 4) {
            #pragma unroll
            for (int d = 0; d < D_DIM; d++) {
                float xv = xw[d * 4 + lid];
                Aj += xv * xv;
            }
        }
        float A[4];
        #pragma unroll
        for (int j = 0; j < 4; j++) A[j] = __shfl_sync(0xffffffffu, Aj, j);

        // 64 accumulators: s[j][i], code k = lid + 32i; fmaf ascending in d
        float s[4][16];
        #pragma unroll
        for (int j = 0; j < 4; j++)
            #pragma unroll
            for (int i = 0; i < 16; i++) s[j][i] = 0.0f;

        for (int d = 0; d < D_DIM; d++) {
            float xv[4];
            #pragma unroll
            for (int j = 0; j < 4; j++) xv[j] = xw[d * 4 + j];   // smem broadcast
            const float* wr = w2 + d * K_CODES + lid;            // conflict-free LDS
            #pragma unroll
            for (int i = 0; i < 16; i++) {
                float wv = wr[i * 32];
                #pragma unroll
                for (int j = 0; j < 4; j++) s[j][i] = fmaf(xv[j], wv, s[j][i]);
            }
        }

        // per pixel: first strict min over k, lexicographic across lanes
        #pragma unroll
        for (int j = 0; j < 4; j++) {
            float bd = CUDART_INF_F; int bk = 0;
            #pragma unroll
            for (int i = 0; i < 16; i++) {
                int k = lid + (i << 5);
                float t = (A[j] + Bsp[k]) - 2.0f * s[j][i];
                if (t < bd) { bd = t; bk = k; }
            }
            #pragma unroll
            for (int off = 16; off > 0; off >>= 1) {
                float od = __shfl_xor_sync(0xffffffffu, bd, off);
                int   ok = __shfl_xor_sync(0xffffffffu, bk, off);
                if (od < bd || (od == bd && ok < bk)) { bd = od; bk = ok; }
            }

            float lsum = 0.0f;
            if (valid[j]) {
                int p = pe[j], bb = p >> 12, hw = p & 4095;
                if (lid == 0) {
                    if (out_idx_f) out_idx_f[p] = (float)bk;
                    if (out_enc && bk != ke[j]) {
                        out_enc[(size_t)p * K_CODES + ke[j]] = 0.0f;
                        out_enc[(size_t)p * K_CODES + bk]   = 1.0f;
                    }
                }
                float* qb = out_q ? out_q + (size_t)bb * (D_DIM * HW) + hw : nullptr;
                #pragma unroll
                for (int u = 0; u < 2; u++) {
                    int d = lid + 32 * u;
                    float diff = W[(size_t)bk * D_DIM + d] - xw[d * 4 + j];
                    if (qb) qb[(size_t)d * HW] = xw[d * 4 + j] + diff;
                    lsum += diff * diff;
                }
            }
            #pragma unroll
            for (int off = 16; off > 0; off >>= 1)
                lsum += __shfl_xor_sync(0xffffffffu, lsum, off);
            if (lid == 0 && valid[j]) atomicAdd(&g_loss_acc, (double)lsum);
        }
        __syncwarp();
    }
}

// ---------------- launch ----------------
extern "C" void kernel_launch(void* const* d_in, const int* in_sizes, int n_in,
                              void* d_out, int out_size)
{
    const float* X = (const float*)d_in[0];
    const float* W = (const float*)d_in[1];
    float* out = (float*)d_out;

    const long long os = (long long)out_size;
    const long long FULL    = 1LL + NQ + ENC_SZ + N_PIX;
    const long long NO_LOSS = (long long)NQ + ENC_SZ + N_PIX;

    float* p_loss = nullptr; float* p_q = nullptr;
    float* p_enc  = nullptr; float* p_idxf = nullptr;

    if (os == FULL) {
        p_loss = out; p_q = out + 1; p_enc = out + 1 + NQ;
        p_idxf = out + 1 + NQ + ENC_SZ;
    } else if (os == NO_LOSS) {
        p_q = out; p_enc = out + NQ; p_idxf = out + NQ + ENC_SZ;
    } else if (os == NQ) {
        p_q = out;
    } else if (os == 1) {
        p_loss = out;
    } else {
        p_loss = out; p_q = out + 1;
        if (os >= 1 + NQ + ENC_SZ) p_enc = out + 1 + NQ;
        if (os >= FULL) p_idxf = out + 1 + NQ + ENC_SZ;
    }

    cudaFuncSetAttribute(vq_mma_kernel,
                         cudaFuncAttributeMaxDynamicSharedMemorySize, SM_TOTAL);
    cudaFuncSetAttribute(rescore_kernel,
                         cudaFuncAttributeMaxDynamicSharedMemorySize, RS_SMEM);

    prep_kernel<<<64, 512>>>(W);
    vq_mma_kernel<<<N_PIX / 256, 512, SM_TOTAL>>>(X, W, p_q, p_enc, p_idxf);
    rescore_kernel<<<RS_BLOCKS, 384, RS_SMEM>>>(X, W, p_q, p_enc, p_idxf);
    if (p_loss) finalize_kernel<<<1, 1>>>(p_loss);
}